// round 3
// baseline (speedup 1.0000x reference)
#include <cuda_runtime.h>

#define VOCAB 50257
#define NT 512
#define NFULL 98                 // j = 0..97 always in-bounds (97*512+511 = 50175 < VOCAB)
#define EPT 99
#define T0 4.0f                  // candidate pre-filter; k-th largest is ~7.4 +/- 0.14
#define CBUF 3072
#define WMAX 128
#define GS_BYTES ((VOCAB * 4 + 15) & ~15)   // 201040

#define NEG_SENT -3.402823466e38f

struct Scratch {
    int      sredi[17];
    float    sredf[17];
    float    cbuf[CBUF];
    float    wbuf[WMAX + 32];
    int      ccnt;
    int      wcnt;
    float    thrslot;
};

#define SMEM_TOTAL (GS_BYTES + (int)sizeof(Scratch))

// ---- order-preserving float <-> u32 key (fallback path only) ----
__device__ __forceinline__ unsigned fkey(float f) {
    unsigned b = __float_as_uint(f);
    unsigned m = (unsigned)(((int)b) >> 31) | 0x80000000u;
    return b ^ m;
}
__device__ __forceinline__ float keyf(unsigned k) {
    unsigned m = (~(unsigned)(((int)k) >> 31)) | 0x80000000u;
    return __uint_as_float(k ^ m);
}

// ---- block reductions (512 threads = 16 warps) ----
__device__ __forceinline__ int blockSumI(int v, int* s) {
    #pragma unroll
    for (int o = 16; o; o >>= 1) v += __shfl_xor_sync(0xffffffffu, v, o);
    int wid = threadIdx.x >> 5, lane = threadIdx.x & 31;
    if (lane == 0) s[wid] = v;
    __syncthreads();
    if (wid == 0) {
        int x = (lane < (NT / 32)) ? s[lane] : 0;
        #pragma unroll
        for (int o = 8; o; o >>= 1) x += __shfl_xor_sync(0xffffffffu, x, o);
        if (lane == 0) s[16] = x;
    }
    __syncthreads();
    int r = s[16];
    __syncthreads();
    return r;
}

__device__ __forceinline__ float blockMaxF(float v, float* s) {
    #pragma unroll
    for (int o = 16; o; o >>= 1) v = fmaxf(v, __shfl_xor_sync(0xffffffffu, v, o));
    int wid = threadIdx.x >> 5, lane = threadIdx.x & 31;
    if (lane == 0) s[wid] = v;
    __syncthreads();
    if (wid == 0) {
        float x = (lane < (NT / 32)) ? s[lane] : NEG_SENT;
        #pragma unroll
        for (int o = 8; o; o >>= 1) x = fmaxf(x, __shfl_xor_sync(0xffffffffu, x, o));
        if (lane == 0) s[16] = x;
    }
    __syncthreads();
    float r = s[16];
    __syncthreads();
    return r;
}

__device__ __forceinline__ float blockSumF(float v, float* s) {
    #pragma unroll
    for (int o = 16; o; o >>= 1) v += __shfl_xor_sync(0xffffffffu, v, o);
    int wid = threadIdx.x >> 5, lane = threadIdx.x & 31;
    if (lane == 0) s[wid] = v;
    __syncthreads();
    if (wid == 0) {
        float x = (lane < (NT / 32)) ? s[lane] : 0.0f;
        #pragma unroll
        for (int o = 8; o; o >>= 1) x += __shfl_xor_sync(0xffffffffu, x, o);
        if (lane == 0) s[16] = x;
    }
    __syncthreads();
    float r = s[16];
    __syncthreads();
    return r;
}

// noise = -log(-log(u + EPS) + EPS), with an exact log1p polynomial for u near 1
// (u -> 1 is exactly the top-k-defining region; MUFU LG2's absolute error there
//  would otherwise amplify to ~1e-2 in the noise).
__device__ __forceinline__ float gumbel_noise(float uu) {
    float vlog = -__logf(uu + 1e-10f);
    float d = uu - 1.0f;                         // exact (Sterbenz) for uu in [0.5, 2)
    float p = __fmaf_rn(-0.25f, d, 0.33333333f); // log1p(d) = d*(1 - d/2 + d^2/3 - d^3/4)
    p = __fmaf_rn(p, d, -0.5f);
    p = __fmaf_rn(p, d, 1.0f);
    float vpoly = -(d * p);
    float v = (uu > 0.99f) ? vpoly : vlog;
    return -__logf(v + 1e-10f);
}

// warp-aggregated candidate push. MUST be called by all 32 lanes of a
// fully-converged warp (use g = NEG_SENT for inactive lanes).
__device__ __forceinline__ void push_cand(float g, Scratch* sc) {
    unsigned act = __ballot_sync(0xffffffffu, g >= T0);
    if (g >= T0) {
        int lane = threadIdx.x & 31;
        int rank = __popc(act & ((1u << lane) - 1u));
        int leader = __ffs(act) - 1;
        int base = 0;
        if (lane == leader) base = atomicAdd(&sc->ccnt, __popc(act));
        base = __shfl_sync(act, base, leader);
        int p = base + rank;
        if (p < CBUF) sc->cbuf[p] = g;
    }
}

__global__ void __launch_bounds__(NT, 1)
gumbel_sampler_kernel(const float* __restrict__ logits,
                      const float* __restrict__ uin,
                      const int* __restrict__ kp,
                      float* __restrict__ out)
{
    extern __shared__ unsigned char smem_raw[];
    float*   gs = (float*)smem_raw;
    Scratch* sc = (Scratch*)(smem_raw + GS_BYTES);

    const int row = blockIdx.x;
    const int tid = threadIdx.x;
    const float* __restrict__ lrow = logits + (size_t)row * VOCAB;
    const float* __restrict__ urow = uin    + (size_t)row * VOCAB;
    float* __restrict__ orow = out + (size_t)row * VOCAB;
    const int k = *kp;

    if (tid == 0) { sc->ccnt = 0; }
    __syncthreads();   // ccnt=0 visible before any push_cand atomic

    float lreg[EPT];

    // ------- P1: load + gumbel; g -> smem; candidates (g>=T0) pushed inline -------
    // Main loop: all NT threads in-bounds every iteration -> warp-converged ballots.
    #pragma unroll 4
    for (int j = 0; j < NFULL; ++j) {
        int idx = tid + j * NT;
        float l = lrow[idx];
        float g = l + gumbel_noise(urow[idx]);
        lreg[j] = l;
        gs[idx] = g;
        push_cand(g, sc);
    }
    // Tail: ALL threads execute (converged); inactive lanes push a sentinel.
    {
        int idx = tid + NFULL * NT;
        float g = NEG_SENT;
        if (idx < VOCAB) {
            float l = lrow[idx];
            g = l + gumbel_noise(urow[idx]);
            lreg[NFULL] = l;
            gs[idx] = g;
        }
        push_cand(g, sc);
    }
    __syncthreads();

    // ---------------- P2: exact k-th largest ----------------
    int m = sc->ccnt;
    float thr;

    if (m >= k && m <= CBUF) {
        // bisection on positive-float bit space over the candidate buffer
        unsigned lo = __float_as_uint(T0);
        unsigned hi = 0x7F800000u;           // +inf
        int c_lo = m, c_hi = 0;
        while ((hi - lo) > 1u && (c_lo - c_hi) > WMAX) {
            unsigned mid = lo + ((hi - lo) >> 1);
            float fm = __uint_as_float(mid);
            int cnt = 0;
            for (int i = tid; i < m; i += NT) cnt += (sc->cbuf[i] >= fm);
            cnt = blockSumI(cnt, sc->sredi);
            if (cnt >= k) { lo = mid; c_lo = cnt; }
            else          { hi = mid; c_hi = cnt; }
        }
        if ((hi - lo) <= 1u) {
            thr = __uint_as_float(lo);
        } else {
            if (tid == 0) sc->wcnt = 0;
            __syncthreads();
            float flo = __uint_as_float(lo), fhi = __uint_as_float(hi);
            for (int i = tid; i < m; i += NT) {
                float v = sc->cbuf[i];
                if (v >= flo && v < fhi) {
                    int p = atomicAdd(&sc->wcnt, 1);
                    if (p < WMAX + 32) sc->wbuf[p] = v;
                }
            }
            __syncthreads();
            int w = sc->wcnt; if (w > WMAX + 32) w = WMAX + 32;
            int need = k - c_hi;
            if (tid < w) {
                float vt = sc->wbuf[tid];
                int gt = 0, ge = 0;
                for (int j = 0; j < w; ++j) {
                    float vj = sc->wbuf[j];
                    gt += (vj >  vt);
                    ge += (vj >= vt);
                }
                if (gt < need && need <= ge) sc->thrslot = vt;
            }
            __syncthreads();
            thr = sc->thrslot;
        }
    } else {
        // fallback (never expected): full bisection over all of gs via order keys
        unsigned lo = 0u, hi = 0xFFFFFFFFu;
        int c_lo = VOCAB, c_hi = 0;
        while ((hi - lo) > 1u && (c_lo - c_hi) > WMAX) {
            unsigned mid = lo + ((hi - lo) >> 1);
            int cnt = 0;
            for (int i = tid; i < VOCAB; i += NT) cnt += (fkey(gs[i]) >= mid);
            cnt = blockSumI(cnt, sc->sredi);
            if (cnt >= k) { lo = mid; c_lo = cnt; }
            else          { hi = mid; c_hi = cnt; }
        }
        if ((hi - lo) <= 1u) {
            thr = keyf(lo);
        } else {
            if (tid == 0) sc->wcnt = 0;
            __syncthreads();
            for (int i = tid; i < VOCAB; i += NT) {
                float v = gs[i];
                unsigned kk = fkey(v);
                if (kk >= lo && kk < hi) {
                    int p = atomicAdd(&sc->wcnt, 1);
                    if (p < WMAX + 32) sc->wbuf[p] = v;
                }
            }
            __syncthreads();
            int w = sc->wcnt; if (w > WMAX + 32) w = WMAX + 32;
            int need = k - c_hi;
            if (tid < w) {
                float vt = sc->wbuf[tid];
                int gt = 0, ge = 0;
                for (int j = 0; j < w; ++j) {
                    float vj = sc->wbuf[j];
                    gt += (vj >  vt);
                    ge += (vj >= vt);
                }
                if (gt < need && need <= ge) sc->thrslot = vt;
            }
            __syncthreads();
            thr = sc->thrslot;
        }
    }

    // ---------------- P3: mask + softmax ----------------
    // Pass A: mk = l * sigmoid(g - thr); overwrite gs with mk; block max.
    float lmax = NEG_SENT;
    #pragma unroll 4
    for (int j = 0; j < NFULL; ++j) {
        int idx = tid + j * NT;
        float g = gs[idx];
        float s = __fdividef(1.0f, 1.0f + __expf(thr - g));
        float mk = lreg[j] * s;
        gs[idx] = mk;
        lmax = fmaxf(lmax, mk);
    }
    {
        int idx = tid + NFULL * NT;
        if (idx < VOCAB) {
            float g = gs[idx];
            float s = __fdividef(1.0f, 1.0f + __expf(thr - g));
            float mk = lreg[NFULL] * s;
            gs[idx] = mk;
            lmax = fmaxf(lmax, mk);
        }
    }
    float M = blockMaxF(lmax, sc->sredf);

    // Pass B: e = exp(mk - M) kept in registers (reusing lreg), block sum.
    float lsum = 0.0f;
    #pragma unroll 4
    for (int j = 0; j < NFULL; ++j) {
        int idx = tid + j * NT;
        float e = __expf(gs[idx] - M);
        lreg[j] = e;
        lsum += e;
    }
    {
        int idx = tid + NFULL * NT;
        if (idx < VOCAB) {
            float e = __expf(gs[idx] - M);
            lreg[NFULL] = e;
            lsum += e;
        }
    }
    float S = blockSumF(lsum, sc->sredf);
    float inv = __fdividef(1.0f, S);

    // Pass C: scaled store straight from registers.
    #pragma unroll 4
    for (int j = 0; j < NFULL; ++j) {
        int idx = tid + j * NT;
        orow[idx] = lreg[j] * inv;
    }
    {
        int idx = tid + NFULL * NT;
        if (idx < VOCAB) orow[idx] = lreg[NFULL] * inv;
    }
}

extern "C" void kernel_launch(void* const* d_in, const int* in_sizes, int n_in,
                              void* d_out, int out_size)
{
    const float* logits = (const float*)d_in[0];
    const float* u      = (const float*)d_in[1];
    const int*   kp     = (const int*)d_in[2];
    float* out = (float*)d_out;

    int B = out_size / VOCAB;

    cudaFuncSetAttribute(gumbel_sampler_kernel,
                         cudaFuncAttributeMaxDynamicSharedMemorySize, SMEM_TOTAL);
    gumbel_sampler_kernel<<<B, NT, SMEM_TOTAL>>>(logits, u, kp, out);
}

// round 4
// speedup vs baseline: 1.1429x; 1.1429x over previous
#include <cuda_runtime.h>

#define VOCAB 50257
#define NT 512
#define NFULL 98                 // j = 0..97 always in-bounds (97*512+511 = 50175 < VOCAB)
#define EPT 99
#define T0 4.0f                  // candidate pre-filter; k-th largest is ~7.4 +/- 0.14
#define CBUF 3072
#define WMAX 128
#define GS_BYTES ((VOCAB * 4 + 15) & ~15)   // 201040

#define NEG_SENT -3.402823466e38f

struct Scratch {
    int      sredi[17];
    float    sredf[17];
    float    cbuf[CBUF];
    float    wbuf[WMAX + 32];
    int      ccnt;
    int      wcnt;
    float    thrslot;
};

#define SMEM_TOTAL (GS_BYTES + (int)sizeof(Scratch))

// ---- order-preserving float <-> u32 key (fallback path only) ----
__device__ __forceinline__ unsigned fkey(float f) {
    unsigned b = __float_as_uint(f);
    unsigned m = (unsigned)(((int)b) >> 31) | 0x80000000u;
    return b ^ m;
}
__device__ __forceinline__ float keyf(unsigned k) {
    unsigned m = (~(unsigned)(((int)k) >> 31)) | 0x80000000u;
    return __uint_as_float(k ^ m);
}

// ---- block reductions (512 threads = 16 warps) ----
__device__ __forceinline__ int blockSumI(int v, int* s) {
    #pragma unroll
    for (int o = 16; o; o >>= 1) v += __shfl_xor_sync(0xffffffffu, v, o);
    int wid = threadIdx.x >> 5, lane = threadIdx.x & 31;
    if (lane == 0) s[wid] = v;
    __syncthreads();
    if (wid == 0) {
        int x = (lane < (NT / 32)) ? s[lane] : 0;
        #pragma unroll
        for (int o = 8; o; o >>= 1) x += __shfl_xor_sync(0xffffffffu, x, o);
        if (lane == 0) s[16] = x;
    }
    __syncthreads();
    int r = s[16];
    __syncthreads();
    return r;
}

__device__ __forceinline__ float blockMaxF(float v, float* s) {
    #pragma unroll
    for (int o = 16; o; o >>= 1) v = fmaxf(v, __shfl_xor_sync(0xffffffffu, v, o));
    int wid = threadIdx.x >> 5, lane = threadIdx.x & 31;
    if (lane == 0) s[wid] = v;
    __syncthreads();
    if (wid == 0) {
        float x = (lane < (NT / 32)) ? s[lane] : NEG_SENT;
        #pragma unroll
        for (int o = 8; o; o >>= 1) x = fmaxf(x, __shfl_xor_sync(0xffffffffu, x, o));
        if (lane == 0) s[16] = x;
    }
    __syncthreads();
    float r = s[16];
    __syncthreads();
    return r;
}

__device__ __forceinline__ float blockSumF(float v, float* s) {
    #pragma unroll
    for (int o = 16; o; o >>= 1) v += __shfl_xor_sync(0xffffffffu, v, o);
    int wid = threadIdx.x >> 5, lane = threadIdx.x & 31;
    if (lane == 0) s[wid] = v;
    __syncthreads();
    if (wid == 0) {
        float x = (lane < (NT / 32)) ? s[lane] : 0.0f;
        #pragma unroll
        for (int o = 8; o; o >>= 1) x += __shfl_xor_sync(0xffffffffu, x, o);
        if (lane == 0) s[16] = x;
    }
    __syncthreads();
    float r = s[16];
    __syncthreads();
    return r;
}

// noise = -log(-log(u + EPS) + EPS), with an exact log1p polynomial for u near 1
// (u -> 1 is exactly the top-k-defining region; MUFU LG2's absolute error there
//  would otherwise amplify to ~1e-2 in the noise).
__device__ __forceinline__ float gumbel_noise(float uu) {
    float vlog = -__logf(uu + 1e-10f);
    float d = uu - 1.0f;                         // exact (Sterbenz) for uu in [0.5, 2)
    float p = __fmaf_rn(-0.25f, d, 0.33333333f); // log1p(d) = d*(1 - d/2 + d^2/3 - d^3/4)
    p = __fmaf_rn(p, d, -0.5f);
    p = __fmaf_rn(p, d, 1.0f);
    float vpoly = -(d * p);
    float v = (uu > 0.99f) ? vpoly : vlog;
    return -__logf(v + 1e-10f);
}

// warp-aggregated candidate push. MUST be called by all 32 lanes of a
// fully-converged warp (use g = NEG_SENT for inactive lanes).
__device__ __forceinline__ void push_cand(float g, Scratch* sc) {
    unsigned act = __ballot_sync(0xffffffffu, g >= T0);
    if (g >= T0) {
        int lane = threadIdx.x & 31;
        int rank = __popc(act & ((1u << lane) - 1u));
        int leader = __ffs(act) - 1;
        int base = 0;
        if (lane == leader) base = atomicAdd(&sc->ccnt, __popc(act));
        base = __shfl_sync(act, base, leader);
        int p = base + rank;
        if (p < CBUF) sc->cbuf[p] = g;
    }
}

__global__ void __launch_bounds__(NT, 1)
gumbel_sampler_kernel(const float* __restrict__ logits,
                      const float* __restrict__ uin,
                      const int* __restrict__ kp,
                      float* __restrict__ out)
{
    extern __shared__ unsigned char smem_raw[];
    float*   gs = (float*)smem_raw;
    Scratch* sc = (Scratch*)(smem_raw + GS_BYTES);

    const int row = blockIdx.x;
    const int tid = threadIdx.x;
    const float* __restrict__ lrow = logits + (size_t)row * VOCAB;
    const float* __restrict__ urow = uin    + (size_t)row * VOCAB;
    float* __restrict__ orow = out + (size_t)row * VOCAB;
    const int k = *kp;

    if (tid == 0) { sc->ccnt = 0; }
    __syncthreads();   // ccnt=0 visible before any push_cand atomic

    float lreg[EPT];

    // ------- P1: load + gumbel; g -> smem; candidates (g>=T0) pushed inline -------
    // FULL unroll is load-bearing: lreg[] must stay in registers (partial unroll
    // demotes it to local memory -> 2x regression, see R3 post-mortem).
    #pragma unroll
    for (int j = 0; j < NFULL; ++j) {
        int idx = tid + j * NT;
        float l = lrow[idx];
        float g = l + gumbel_noise(urow[idx]);
        lreg[j] = l;
        gs[idx] = g;
        push_cand(g, sc);
    }
    // Tail: ALL threads execute (converged); inactive lanes push a sentinel.
    {
        int idx = tid + NFULL * NT;
        float g = NEG_SENT;
        if (idx < VOCAB) {
            float l = lrow[idx];
            g = l + gumbel_noise(urow[idx]);
            lreg[NFULL] = l;
            gs[idx] = g;
        }
        push_cand(g, sc);
    }
    __syncthreads();

    // ---------------- P2: exact k-th largest ----------------
    int m = sc->ccnt;
    float thr;

    if (m >= k && m <= CBUF) {
        // bisection on positive-float bit space over the candidate buffer
        unsigned lo = __float_as_uint(T0);
        unsigned hi = 0x7F800000u;           // +inf
        int c_lo = m, c_hi = 0;
        while ((hi - lo) > 1u && (c_lo - c_hi) > WMAX) {
            unsigned mid = lo + ((hi - lo) >> 1);
            float fm = __uint_as_float(mid);
            int cnt = 0;
            for (int i = tid; i < m; i += NT) cnt += (sc->cbuf[i] >= fm);
            cnt = blockSumI(cnt, sc->sredi);
            if (cnt >= k) { lo = mid; c_lo = cnt; }
            else          { hi = mid; c_hi = cnt; }
        }
        if ((hi - lo) <= 1u) {
            thr = __uint_as_float(lo);
        } else {
            if (tid == 0) sc->wcnt = 0;
            __syncthreads();
            float flo = __uint_as_float(lo), fhi = __uint_as_float(hi);
            for (int i = tid; i < m; i += NT) {
                float v = sc->cbuf[i];
                if (v >= flo && v < fhi) {
                    int p = atomicAdd(&sc->wcnt, 1);
                    if (p < WMAX + 32) sc->wbuf[p] = v;
                }
            }
            __syncthreads();
            int w = sc->wcnt; if (w > WMAX + 32) w = WMAX + 32;
            int need = k - c_hi;
            if (tid < w) {
                float vt = sc->wbuf[tid];
                int gt = 0, ge = 0;
                for (int j = 0; j < w; ++j) {
                    float vj = sc->wbuf[j];
                    gt += (vj >  vt);
                    ge += (vj >= vt);
                }
                if (gt < need && need <= ge) sc->thrslot = vt;
            }
            __syncthreads();
            thr = sc->thrslot;
        }
    } else {
        // fallback (never expected): full bisection over all of gs via order keys
        unsigned lo = 0u, hi = 0xFFFFFFFFu;
        int c_lo = VOCAB, c_hi = 0;
        while ((hi - lo) > 1u && (c_lo - c_hi) > WMAX) {
            unsigned mid = lo + ((hi - lo) >> 1);
            int cnt = 0;
            for (int i = tid; i < VOCAB; i += NT) cnt += (fkey(gs[i]) >= mid);
            cnt = blockSumI(cnt, sc->sredi);
            if (cnt >= k) { lo = mid; c_lo = cnt; }
            else          { hi = mid; c_hi = cnt; }
        }
        if ((hi - lo) <= 1u) {
            thr = keyf(lo);
        } else {
            if (tid == 0) sc->wcnt = 0;
            __syncthreads();
            for (int i = tid; i < VOCAB; i += NT) {
                float v = gs[i];
                unsigned kk = fkey(v);
                if (kk >= lo && kk < hi) {
                    int p = atomicAdd(&sc->wcnt, 1);
                    if (p < WMAX + 32) sc->wbuf[p] = v;
                }
            }
            __syncthreads();
            int w = sc->wcnt; if (w > WMAX + 32) w = WMAX + 32;
            int need = k - c_hi;
            if (tid < w) {
                float vt = sc->wbuf[tid];
                int gt = 0, ge = 0;
                for (int j = 0; j < w; ++j) {
                    float vj = sc->wbuf[j];
                    gt += (vj >  vt);
                    ge += (vj >= vt);
                }
                if (gt < need && need <= ge) sc->thrslot = vt;
            }
            __syncthreads();
            thr = sc->thrslot;
        }
    }

    // ---------------- P3: mask + softmax ----------------
    // Pass A: mk = l * sigmoid(g - thr); overwrite gs with mk; block max.
    float lmax = NEG_SENT;
    #pragma unroll
    for (int j = 0; j < NFULL; ++j) {
        int idx = tid + j * NT;
        float g = gs[idx];
        float s = __fdividef(1.0f, 1.0f + __expf(thr - g));
        float mk = lreg[j] * s;
        gs[idx] = mk;
        lmax = fmaxf(lmax, mk);
    }
    {
        int idx = tid + NFULL * NT;
        if (idx < VOCAB) {
            float g = gs[idx];
            float s = __fdividef(1.0f, 1.0f + __expf(thr - g));
            float mk = lreg[NFULL] * s;
            gs[idx] = mk;
            lmax = fmaxf(lmax, mk);
        }
    }
    float M = blockMaxF(lmax, sc->sredf);

    // Pass B: e = exp(mk - M) kept in registers (reusing lreg), block sum.
    float lsum = 0.0f;
    #pragma unroll
    for (int j = 0; j < NFULL; ++j) {
        int idx = tid + j * NT;
        float e = __expf(gs[idx] - M);
        lreg[j] = e;
        lsum += e;
    }
    {
        int idx = tid + NFULL * NT;
        if (idx < VOCAB) {
            float e = __expf(gs[idx] - M);
            lreg[NFULL] = e;
            lsum += e;
        }
    }
    float S = blockSumF(lsum, sc->sredf);
    float inv = __fdividef(1.0f, S);

    // Pass C: scaled store straight from registers.
    #pragma unroll
    for (int j = 0; j < NFULL; ++j) {
        int idx = tid + j * NT;
        orow[idx] = lreg[j] * inv;
    }
    {
        int idx = tid + NFULL * NT;
        if (idx < VOCAB) orow[idx] = lreg[NFULL] * inv;
    }
}

extern "C" void kernel_launch(void* const* d_in, const int* in_sizes, int n_in,
                              void* d_out, int out_size)
{
    const float* logits = (const float*)d_in[0];
    const float* u      = (const float*)d_in[1];
    const int*   kp     = (const int*)d_in[2];
    float* out = (float*)d_out;

    int B = out_size / VOCAB;

    cudaFuncSetAttribute(gumbel_sampler_kernel,
                         cudaFuncAttributeMaxDynamicSharedMemorySize, SMEM_TOTAL);
    gumbel_sampler_kernel<<<B, NT, SMEM_TOTAL>>>(logits, u, kp, out);
}

// round 5
// speedup vs baseline: 2.5771x; 2.2549x over previous
#include <cuda_runtime.h>

#define VOCAB 50257
#define NT 512
#define NFULL 98                 // j = 0..97 always in-bounds (97*512+511 = 50175 < VOCAB)
#define EPT 99
#define T0 4.0f                  // candidate pre-filter; k-th largest is ~7.4 +/- 0.14
#define CBUF 3072
#define WMAX 128
#define GS_BYTES ((VOCAB * 4 + 15) & ~15)   // 201040

#define NEG_SENT -3.402823466e38f

struct Scratch {
    int      sredi[17];
    float    sredf[17];
    int      sscan[17];
    float    cbuf[CBUF];
    float    wbuf[WMAX + 32];
    int      wcnt;
    float    thrslot;
};

#define SMEM_TOTAL (GS_BYTES + (int)sizeof(Scratch))

// ---- order-preserving float <-> u32 key (fallback path only) ----
__device__ __forceinline__ unsigned fkey(float f) {
    unsigned b = __float_as_uint(f);
    unsigned m = (unsigned)(((int)b) >> 31) | 0x80000000u;
    return b ^ m;
}
__device__ __forceinline__ float keyf(unsigned k) {
    unsigned m = (~(unsigned)(((int)k) >> 31)) | 0x80000000u;
    return __uint_as_float(k ^ m);
}

// ---- block reductions (512 threads = 16 warps) ----
__device__ __forceinline__ int blockSumI(int v, int* s) {
    #pragma unroll
    for (int o = 16; o; o >>= 1) v += __shfl_xor_sync(0xffffffffu, v, o);
    int wid = threadIdx.x >> 5, lane = threadIdx.x & 31;
    if (lane == 0) s[wid] = v;
    __syncthreads();
    if (wid == 0) {
        int x = (lane < (NT / 32)) ? s[lane] : 0;
        #pragma unroll
        for (int o = 8; o; o >>= 1) x += __shfl_xor_sync(0xffffffffu, x, o);
        if (lane == 0) s[16] = x;
    }
    __syncthreads();
    int r = s[16];
    __syncthreads();
    return r;
}

__device__ __forceinline__ float blockMaxF(float v, float* s) {
    #pragma unroll
    for (int o = 16; o; o >>= 1) v = fmaxf(v, __shfl_xor_sync(0xffffffffu, v, o));
    int wid = threadIdx.x >> 5, lane = threadIdx.x & 31;
    if (lane == 0) s[wid] = v;
    __syncthreads();
    if (wid == 0) {
        float x = (lane < (NT / 32)) ? s[lane] : NEG_SENT;
        #pragma unroll
        for (int o = 8; o; o >>= 1) x = fmaxf(x, __shfl_xor_sync(0xffffffffu, x, o));
        if (lane == 0) s[16] = x;
    }
    __syncthreads();
    float r = s[16];
    __syncthreads();
    return r;
}

__device__ __forceinline__ float blockSumF(float v, float* s) {
    #pragma unroll
    for (int o = 16; o; o >>= 1) v += __shfl_xor_sync(0xffffffffu, v, o);
    int wid = threadIdx.x >> 5, lane = threadIdx.x & 31;
    if (lane == 0) s[wid] = v;
    __syncthreads();
    if (wid == 0) {
        float x = (lane < (NT / 32)) ? s[lane] : 0.0f;
        #pragma unroll
        for (int o = 8; o; o >>= 1) x += __shfl_xor_sync(0xffffffffu, x, o);
        if (lane == 0) s[16] = x;
    }
    __syncthreads();
    float r = s[16];
    __syncthreads();
    return r;
}

// exclusive prefix over 512 threads; total left in s[16]
__device__ __forceinline__ int blockExclScan(int c, int* s) {
    int lane = threadIdx.x & 31, wid = threadIdx.x >> 5;
    int inc = c;
    #pragma unroll
    for (int o = 1; o < 32; o <<= 1) {
        int t = __shfl_up_sync(0xffffffffu, inc, o);
        if (lane >= o) inc += t;
    }
    if (lane == 31) s[wid] = inc;
    __syncthreads();
    if (wid == 0) {
        int w = (lane < 16) ? s[lane] : 0;
        #pragma unroll
        for (int o = 1; o < 16; o <<= 1) {
            int t = __shfl_up_sync(0xffffffffu, w, o);
            if (lane >= o) w += t;
        }
        if (lane < 16) s[lane] = w;      // inclusive warp totals
        if (lane == 15) s[16] = w;       // grand total
    }
    __syncthreads();
    int base = (wid == 0) ? 0 : s[wid - 1];
    return base + inc - c;
}

// noise = -log(-log(u + EPS) + EPS), with an exact log1p polynomial for u near 1
// (u -> 1 is exactly the top-k-defining region; MUFU LG2's absolute error there
//  would otherwise amplify to ~1e-2 in the noise).
__device__ __forceinline__ float gumbel_noise(float uu) {
    float vlog = -__logf(uu + 1e-10f);
    float d = uu - 1.0f;                         // exact (Sterbenz) for uu in [0.5, 2)
    float p = __fmaf_rn(-0.25f, d, 0.33333333f); // log1p(d) = d*(1 - d/2 + d^2/3 - d^3/4)
    p = __fmaf_rn(p, d, -0.5f);
    p = __fmaf_rn(p, d, 1.0f);
    float vpoly = -(d * p);
    float v = (uu > 0.99f) ? vpoly : vlog;
    return -__logf(v + 1e-10f);
}

__global__ void __launch_bounds__(NT, 1)
gumbel_sampler_kernel(const float* __restrict__ logits,
                      const float* __restrict__ uin,
                      const int* __restrict__ kp,
                      float* __restrict__ out)
{
    extern __shared__ unsigned char smem_raw[];
    float*   gs = (float*)smem_raw;
    Scratch* sc = (Scratch*)(smem_raw + GS_BYTES);

    const int row = blockIdx.x;
    const int tid = threadIdx.x;
    const float* __restrict__ lrow = logits + (size_t)row * VOCAB;
    const float* __restrict__ urow = uin    + (size_t)row * VOCAB;
    float* __restrict__ orow = out + (size_t)row * VOCAB;
    const int k = *kp;

    float lreg[EPT];
    int cnt = 0;

    // ------- P1: load + gumbel; g -> smem; logits -> registers; count g>=T0 -------
    // FULL unroll is load-bearing: lreg[] must stay in registers (partial unroll
    // demotes it to local memory -> 2x regression, see R3 post-mortem).
    #pragma unroll
    for (int j = 0; j < NFULL; ++j) {
        int idx = tid + j * NT;
        float l = lrow[idx];
        float g = l + gumbel_noise(urow[idx]);
        lreg[j] = l;
        gs[idx] = g;
        cnt += (g >= T0);
    }
    {
        int idx = tid + NFULL * NT;
        if (idx < VOCAB) {
            float l = lrow[idx];
            float g = l + gumbel_noise(urow[idx]);
            lreg[NFULL] = l;
            gs[idx] = g;
            cnt += (g >= T0);
        }
    }
    __syncthreads();

    // ------- P2a: dense candidate compaction (scan + predicated placement) -------
    int pos = blockExclScan(cnt, sc->sscan);
    int m = sc->sscan[16];

    if (m >= k && m <= CBUF) {
        // placement sweep: each thread re-reads its own strided elements
        #pragma unroll 8
        for (int j = 0; j < NFULL; ++j) {
            float g = gs[tid + j * NT];
            if (g >= T0) sc->cbuf[pos++] = g;   // predicated STS + IADD, no atomics
        }
        {
            int idx = tid + NFULL * NT;
            if (idx < VOCAB) {
                float g = gs[idx];
                if (g >= T0) sc->cbuf[pos++] = g;
            }
        }
        __syncthreads();
    }

    // ---------------- P2b: exact k-th largest ----------------
    float thr;

    if (m >= k && m <= CBUF) {
        // bisection on positive-float bit space over the candidate buffer
        unsigned lo = __float_as_uint(T0);
        unsigned hi = 0x7F800000u;           // +inf
        int c_lo = m, c_hi = 0;
        while ((hi - lo) > 1u && (c_lo - c_hi) > WMAX) {
            unsigned mid = lo + ((hi - lo) >> 1);
            float fm = __uint_as_float(mid);
            int c = 0;
            for (int i = tid; i < m; i += NT) c += (sc->cbuf[i] >= fm);
            c = blockSumI(c, sc->sredi);
            if (c >= k) { lo = mid; c_lo = c; }
            else        { hi = mid; c_hi = c; }
        }
        if ((hi - lo) <= 1u) {
            thr = __uint_as_float(lo);
        } else {
            if (tid == 0) sc->wcnt = 0;
            __syncthreads();
            float flo = __uint_as_float(lo), fhi = __uint_as_float(hi);
            for (int i = tid; i < m; i += NT) {
                float v = sc->cbuf[i];
                if (v >= flo && v < fhi) {
                    int p = atomicAdd(&sc->wcnt, 1);
                    if (p < WMAX + 32) sc->wbuf[p] = v;
                }
            }
            __syncthreads();
            int w = sc->wcnt; if (w > WMAX + 32) w = WMAX + 32;
            int need = k - c_hi;
            if (tid < w) {
                float vt = sc->wbuf[tid];
                int gt = 0, ge = 0;
                for (int j = 0; j < w; ++j) {
                    float vj = sc->wbuf[j];
                    gt += (vj >  vt);
                    ge += (vj >= vt);
                }
                if (gt < need && need <= ge) sc->thrslot = vt;
            }
            __syncthreads();
            thr = sc->thrslot;
        }
    } else {
        // fallback (never expected): full bisection over all of gs via order keys
        unsigned lo = 0u, hi = 0xFFFFFFFFu;
        int c_lo = VOCAB, c_hi = 0;
        while ((hi - lo) > 1u && (c_lo - c_hi) > WMAX) {
            unsigned mid = lo + ((hi - lo) >> 1);
            int c = 0;
            for (int i = tid; i < VOCAB; i += NT) c += (fkey(gs[i]) >= mid);
            c = blockSumI(c, sc->sredi);
            if (c >= k) { lo = mid; c_lo = c; }
            else        { hi = mid; c_hi = c; }
        }
        if ((hi - lo) <= 1u) {
            thr = keyf(lo);
        } else {
            if (tid == 0) sc->wcnt = 0;
            __syncthreads();
            for (int i = tid; i < VOCAB; i += NT) {
                float v = gs[i];
                unsigned kk = fkey(v);
                if (kk >= lo && kk < hi) {
                    int p = atomicAdd(&sc->wcnt, 1);
                    if (p < WMAX + 32) sc->wbuf[p] = v;
                }
            }
            __syncthreads();
            int w = sc->wcnt; if (w > WMAX + 32) w = WMAX + 32;
            int need = k - c_hi;
            if (tid < w) {
                float vt = sc->wbuf[tid];
                int gt = 0, ge = 0;
                for (int j = 0; j < w; ++j) {
                    float vj = sc->wbuf[j];
                    gt += (vj >  vt);
                    ge += (vj >= vt);
                }
                if (gt < need && need <= ge) sc->thrslot = vt;
            }
            __syncthreads();
            thr = sc->thrslot;
        }
    }

    // ---------------- P3: mask + softmax (register-resident, 1 smem read pass) ----
    // Pass A: mk = l * sigmoid(g - thr) overwrites lreg; block max.
    float lmax = NEG_SENT;
    #pragma unroll
    for (int j = 0; j < NFULL; ++j) {
        int idx = tid + j * NT;
        float g = gs[idx];
        float s = __fdividef(1.0f, 1.0f + __expf(thr - g));
        float mk = lreg[j] * s;
        lreg[j] = mk;
        lmax = fmaxf(lmax, mk);
    }
    {
        int idx = tid + NFULL * NT;
        if (idx < VOCAB) {
            float g = gs[idx];
            float s = __fdividef(1.0f, 1.0f + __expf(thr - g));
            float mk = lreg[NFULL] * s;
            lreg[NFULL] = mk;
            lmax = fmaxf(lmax, mk);
        }
    }
    float M = blockMaxF(lmax, sc->sredf);

    // Pass B: e = exp(mk - M), registers only; block sum.
    float lsum = 0.0f;
    #pragma unroll
    for (int j = 0; j < NFULL; ++j) {
        float e = __expf(lreg[j] - M);
        lreg[j] = e;
        lsum += e;
    }
    {
        int idx = tid + NFULL * NT;
        if (idx < VOCAB) {
            float e = __expf(lreg[NFULL] - M);
            lreg[NFULL] = e;
            lsum += e;
        }
    }
    float S = blockSumF(lsum, sc->sredf);
    float inv = __fdividef(1.0f, S);

    // Pass C: scaled store straight from registers.
    #pragma unroll
    for (int j = 0; j < NFULL; ++j) {
        int idx = tid + j * NT;
        orow[idx] = lreg[j] * inv;
    }
    {
        int idx = tid + NFULL * NT;
        if (idx < VOCAB) orow[idx] = lreg[NFULL] * inv;
    }
}

extern "C" void kernel_launch(void* const* d_in, const int* in_sizes, int n_in,
                              void* d_out, int out_size)
{
    const float* logits = (const float*)d_in[0];
    const float* u      = (const float*)d_in[1];
    const int*   kp     = (const int*)d_in[2];
    float* out = (float*)d_out;

    int B = out_size / VOCAB;

    cudaFuncSetAttribute(gumbel_sampler_kernel,
                         cudaFuncAttributeMaxDynamicSharedMemorySize, SMEM_TOTAL);
    gumbel_sampler_kernel<<<B, NT, SMEM_TOTAL>>>(logits, u, kp, out);
}

// round 6
// speedup vs baseline: 3.1723x; 1.2310x over previous
#include <cuda_runtime.h>

#define VOCAB 50257
#define NT 512
#define NFULL 98                 // j = 0..97 always in-bounds (97*512+511 = 50175 < VOCAB)
#define EPT 99
#define T0 4.0f                  // candidate pre-filter; k-th largest is ~7.4 +/- 0.14
#define T0_BITS 0x40800000u      // bits of 4.0f
#define NBIN 384                 // [4,32) in (1<<16)-ulp bins, monotone in g
#define WCAP 256                 // in-bin select capacity
#define WMAX 128                 // fallback bisection window
#define GS_BYTES ((VOCAB * 4 + 15) & ~15)   // 201040

#define NEG_SENT -3.402823466e38f

struct Scratch {
    int      sredi[17];
    float    sredf[17];
    int      sscan[17];
    int      hist[NBIN];
    int      suffix[NBIN + 1];
    float    wbuf[WCAP + 32];
    int      wcnt;
    int      binid;
    float    thrslot;
};

#define SMEM_TOTAL (GS_BYTES + (int)sizeof(Scratch))

// ---- order-preserving float <-> u32 key (fallback path only) ----
__device__ __forceinline__ unsigned fkey(float f) {
    unsigned b = __float_as_uint(f);
    unsigned m = (unsigned)(((int)b) >> 31) | 0x80000000u;
    return b ^ m;
}
__device__ __forceinline__ float keyf(unsigned k) {
    unsigned m = (~(unsigned)(((int)k) >> 31)) | 0x80000000u;
    return __uint_as_float(k ^ m);
}

// ---- block reductions (512 threads = 16 warps) ----
__device__ __forceinline__ int blockSumI(int v, int* s) {
    #pragma unroll
    for (int o = 16; o; o >>= 1) v += __shfl_xor_sync(0xffffffffu, v, o);
    int wid = threadIdx.x >> 5, lane = threadIdx.x & 31;
    if (lane == 0) s[wid] = v;
    __syncthreads();
    if (wid == 0) {
        int x = (lane < (NT / 32)) ? s[lane] : 0;
        #pragma unroll
        for (int o = 8; o; o >>= 1) x += __shfl_xor_sync(0xffffffffu, x, o);
        if (lane == 0) s[16] = x;
    }
    __syncthreads();
    int r = s[16];
    __syncthreads();
    return r;
}

__device__ __forceinline__ float blockMaxF(float v, float* s) {
    #pragma unroll
    for (int o = 16; o; o >>= 1) v = fmaxf(v, __shfl_xor_sync(0xffffffffu, v, o));
    int wid = threadIdx.x >> 5, lane = threadIdx.x & 31;
    if (lane == 0) s[wid] = v;
    __syncthreads();
    if (wid == 0) {
        float x = (lane < (NT / 32)) ? s[lane] : NEG_SENT;
        #pragma unroll
        for (int o = 8; o; o >>= 1) x = fmaxf(x, __shfl_xor_sync(0xffffffffu, x, o));
        if (lane == 0) s[16] = x;
    }
    __syncthreads();
    float r = s[16];
    __syncthreads();
    return r;
}

__device__ __forceinline__ float blockSumF(float v, float* s) {
    #pragma unroll
    for (int o = 16; o; o >>= 1) v += __shfl_xor_sync(0xffffffffu, v, o);
    int wid = threadIdx.x >> 5, lane = threadIdx.x & 31;
    if (lane == 0) s[wid] = v;
    __syncthreads();
    if (wid == 0) {
        float x = (lane < (NT / 32)) ? s[lane] : 0.0f;
        #pragma unroll
        for (int o = 8; o; o >>= 1) x += __shfl_xor_sync(0xffffffffu, x, o);
        if (lane == 0) s[16] = x;
    }
    __syncthreads();
    float r = s[16];
    __syncthreads();
    return r;
}

// exclusive prefix over 512 threads; total left in s[16]
__device__ __forceinline__ int blockExclScan(int c, int* s) {
    int lane = threadIdx.x & 31, wid = threadIdx.x >> 5;
    int inc = c;
    #pragma unroll
    for (int o = 1; o < 32; o <<= 1) {
        int t = __shfl_up_sync(0xffffffffu, inc, o);
        if (lane >= o) inc += t;
    }
    if (lane == 31) s[wid] = inc;
    __syncthreads();
    if (wid == 0) {
        int w = (lane < 16) ? s[lane] : 0;
        #pragma unroll
        for (int o = 1; o < 16; o <<= 1) {
            int t = __shfl_up_sync(0xffffffffu, w, o);
            if (lane >= o) w += t;
        }
        if (lane < 16) s[lane] = w;      // inclusive warp totals
        if (lane == 15) s[16] = w;       // grand total
    }
    __syncthreads();
    int base = (wid == 0) ? 0 : s[wid - 1];
    return base + inc - c;
}

// noise = -log(-log(u + EPS) + EPS), with an exact log1p polynomial for u near 1
// (u -> 1 is exactly the top-k-defining region; MUFU LG2's absolute error there
//  would otherwise amplify to ~1e-2 in the noise).
__device__ __forceinline__ float gumbel_noise(float uu) {
    float vlog = -__logf(uu + 1e-10f);
    float d = uu - 1.0f;                         // exact (Sterbenz) for uu in [0.5, 2)
    float p = __fmaf_rn(-0.25f, d, 0.33333333f); // log1p(d) = d*(1 - d/2 + d^2/3 - d^3/4)
    p = __fmaf_rn(p, d, -0.5f);
    p = __fmaf_rn(p, d, 1.0f);
    float vpoly = -(d * p);
    float v = (uu > 0.99f) ? vpoly : vlog;
    return -__logf(v + 1e-10f);
}

__global__ void __launch_bounds__(NT, 1)
gumbel_sampler_kernel(const float* __restrict__ logits,
                      const float* __restrict__ uin,
                      const int* __restrict__ kp,
                      float* __restrict__ out)
{
    extern __shared__ unsigned char smem_raw[];
    float*   gs = (float*)smem_raw;
    Scratch* sc = (Scratch*)(smem_raw + GS_BYTES);

    const int row = blockIdx.x;
    const int tid = threadIdx.x;
    const float* __restrict__ lrow = logits + (size_t)row * VOCAB;
    const float* __restrict__ urow = uin    + (size_t)row * VOCAB;
    float* __restrict__ orow = out + (size_t)row * VOCAB;
    const int k = *kp;

    if (tid < NBIN) sc->hist[tid] = 0;
    __syncthreads();

    float lreg[EPT];

    // ------- P1: load + gumbel; g -> smem; logits -> registers; histogram g>=T0 ----
    // FULL unroll is load-bearing: lreg[] must stay in registers (partial unroll
    // demotes it to local memory -> 2x regression, see R3 post-mortem).
    #pragma unroll
    for (int j = 0; j < NFULL; ++j) {
        int idx = tid + j * NT;
        float l = __ldcs(lrow + idx);
        float g = l + gumbel_noise(__ldcs(urow + idx));
        lreg[j] = l;
        gs[idx] = g;
        if (g >= T0) {
            unsigned bin = (__float_as_uint(g) - T0_BITS) >> 16;
            if (bin > NBIN - 1) bin = NBIN - 1;
            atomicAdd(&sc->hist[bin], 1);
        }
    }
    {
        int idx = tid + NFULL * NT;
        if (idx < VOCAB) {
            float l = __ldcs(lrow + idx);
            float g = l + gumbel_noise(__ldcs(urow + idx));
            lreg[NFULL] = l;
            gs[idx] = g;
            if (g >= T0) {
                unsigned bin = (__float_as_uint(g) - T0_BITS) >> 16;
                if (bin > NBIN - 1) bin = NBIN - 1;
                atomicAdd(&sc->hist[bin], 1);
            }
        }
    }
    __syncthreads();

    // ------- L2 prefetch of the next wave's row (runs next on this SM) -------
    {
        int pf = row + 148;
        if (pf < (int)gridDim.x) {
            const float* pl = logits + (size_t)pf * VOCAB;
            const float* pu = uin    + (size_t)pf * VOCAB;
            #pragma unroll 1
            for (int i = tid * 32; i < VOCAB; i += NT * 32) {
                asm volatile("prefetch.global.L2 [%0];" :: "l"(pl + i));
                asm volatile("prefetch.global.L2 [%0];" :: "l"(pu + i));
            }
        }
    }

    // ------- P2: suffix-scan the histogram, locate the k-th value's bin -------
    int h = (tid < NBIN) ? sc->hist[tid] : 0;
    int pe = blockExclScan(h, sc->sscan);
    int m = sc->sscan[16];
    if (tid < NBIN) sc->suffix[tid] = m - pe;
    if (tid == 0) { sc->suffix[NBIN] = 0; sc->wcnt = 0; }
    __syncthreads();

    float thr;
    bool mainpath = (m >= k);
    if (mainpath) {
        if (tid < NBIN && sc->suffix[tid] >= k && sc->suffix[tid + 1] < k)
            sc->binid = tid;
        __syncthreads();
        int b    = sc->binid;
        int hb   = sc->hist[b];
        int c_hi = sc->suffix[b + 1];
        if (hb <= WCAP) {
            float flo = __uint_as_float(T0_BITS + ((unsigned)b << 16));
            float fhi = __uint_as_float(T0_BITS + ((unsigned)(b + 1) << 16));
            // single filtered sweep (no lreg access -> partial unroll safe)
            #pragma unroll 8
            for (int j = 0; j < NFULL; ++j) {
                float g = gs[tid + j * NT];
                if (g >= flo && g < fhi) {
                    int p = atomicAdd(&sc->wcnt, 1);
                    if (p < WCAP + 32) sc->wbuf[p] = g;
                }
            }
            {
                int idx = tid + NFULL * NT;
                if (idx < VOCAB) {
                    float g = gs[idx];
                    if (g >= flo && g < fhi) {
                        int p = atomicAdd(&sc->wcnt, 1);
                        if (p < WCAP + 32) sc->wbuf[p] = g;
                    }
                }
            }
            __syncthreads();
            int w = sc->wcnt; if (w > WCAP + 32) w = WCAP + 32;
            int need = k - c_hi;
            if (tid < w) {
                float vt = sc->wbuf[tid];
                int gt = 0, ge = 0;
                for (int j = 0; j < w; ++j) {
                    float vj = sc->wbuf[j];
                    gt += (vj >  vt);
                    ge += (vj >= vt);
                }
                if (gt < need && need <= ge) sc->thrslot = vt;
            }
            __syncthreads();
            thr = sc->thrslot;
        } else {
            mainpath = false;   // uniform across block
        }
    }

    if (!mainpath) {
        // fallback (never expected): full bisection over all of gs via order keys
        unsigned lo = 0u, hi = 0xFFFFFFFFu;
        int c_lo = VOCAB, c_hi = 0;
        while ((hi - lo) > 1u && (c_lo - c_hi) > WMAX) {
            unsigned mid = lo + ((hi - lo) >> 1);
            int c = 0;
            for (int i = tid; i < VOCAB; i += NT) c += (fkey(gs[i]) >= mid);
            c = blockSumI(c, sc->sredi);
            if (c >= k) { lo = mid; c_lo = c; }
            else        { hi = mid; c_hi = c; }
        }
        if ((hi - lo) <= 1u) {
            thr = keyf(lo);
        } else {
            if (tid == 0) sc->wcnt = 0;
            __syncthreads();
            for (int i = tid; i < VOCAB; i += NT) {
                float v = gs[i];
                unsigned kk = fkey(v);
                if (kk >= lo && kk < hi) {
                    int p = atomicAdd(&sc->wcnt, 1);
                    if (p < WMAX + 32) sc->wbuf[p] = v;
                }
            }
            __syncthreads();
            int w = sc->wcnt; if (w > WMAX + 32) w = WMAX + 32;
            int need = k - c_hi;
            if (tid < w) {
                float vt = sc->wbuf[tid];
                int gt = 0, ge = 0;
                for (int j = 0; j < w; ++j) {
                    float vj = sc->wbuf[j];
                    gt += (vj >  vt);
                    ge += (vj >= vt);
                }
                if (gt < need && need <= ge) sc->thrslot = vt;
            }
            __syncthreads();
            thr = sc->thrslot;
        }
    }

    // ---------------- P3: mask + softmax (register-resident, 1 smem read pass) ----
    // Pass A: mk = l * sigmoid(g - thr) overwrites lreg; block max.
    float lmax = NEG_SENT;
    #pragma unroll
    for (int j = 0; j < NFULL; ++j) {
        int idx = tid + j * NT;
        float g = gs[idx];
        float s = __fdividef(1.0f, 1.0f + __expf(thr - g));
        float mk = lreg[j] * s;
        lreg[j] = mk;
        lmax = fmaxf(lmax, mk);
    }
    {
        int idx = tid + NFULL * NT;
        if (idx < VOCAB) {
            float g = gs[idx];
            float s = __fdividef(1.0f, 1.0f + __expf(thr - g));
            float mk = lreg[NFULL] * s;
            lreg[NFULL] = mk;
            lmax = fmaxf(lmax, mk);
        }
    }
    float M = blockMaxF(lmax, sc->sredf);

    // Pass B: e = exp(mk - M), registers only; block sum.
    float lsum = 0.0f;
    #pragma unroll
    for (int j = 0; j < NFULL; ++j) {
        float e = __expf(lreg[j] - M);
        lreg[j] = e;
        lsum += e;
    }
    {
        int idx = tid + NFULL * NT;
        if (idx < VOCAB) {
            float e = __expf(lreg[NFULL] - M);
            lreg[NFULL] = e;
            lsum += e;
        }
    }
    float S = blockSumF(lsum, sc->sredf);
    float inv = __fdividef(1.0f, S);

    // Pass C: scaled streaming store straight from registers (evict-first,
    // protects prefetched next-row lines in L2).
    #pragma unroll
    for (int j = 0; j < NFULL; ++j) {
        int idx = tid + j * NT;
        __stcs(orow + idx, lreg[j] * inv);
    }
    {
        int idx = tid + NFULL * NT;
        if (idx < VOCAB) __stcs(orow + idx, lreg[NFULL] * inv);
    }
}

extern "C" void kernel_launch(void* const* d_in, const int* in_sizes, int n_in,
                              void* d_out, int out_size)
{
    const float* logits = (const float*)d_in[0];
    const float* u      = (const float*)d_in[1];
    const int*   kp     = (const int*)d_in[2];
    float* out = (float*)d_out;

    int B = out_size / VOCAB;

    cudaFuncSetAttribute(gumbel_sampler_kernel,
                         cudaFuncAttributeMaxDynamicSharedMemorySize, SMEM_TOTAL);
    gumbel_sampler_kernel<<<B, NT, SMEM_TOTAL>>>(logits, u, kp, out);
}